// round 9
// baseline (speedup 1.0000x reference)
#include <cuda_runtime.h>
#include <cuda_bf16.h>
#include <cstdint>

#define CC 16
#define LL 8192
#define EE 512
#define HH 256
#define MM 128
#define TOPK 30
#define SSEQ 8191
#define NROWS 131056
#define NT 512

// smem byte offsets
#define HB 0                 // h split: 8 chunks x [hi 8KB | lo 8KB] = 128KB
#define XS 131072            // X split ping-pong: 2 x 16KB
#define WB 163840            // W ping-pong: 2 x 16KB
#define ROWX 196608
#define B1S 197120
#define B2S 198144
#define MB 198656            // 2 mbarriers
#define SMEMB 198784
#define LSTR 132

#define SWZ64(o) ((o) ^ (((o) >> 3) & 0x30))

__device__ unsigned short g_w1pk[262144];  // 512KB: 32 chunks x [hi 8KB | lo 8KB], n-major [128n][32k]
__device__ unsigned short g_w2pk[65536];   // 128KB: 8 chunks x [hi | lo]

__device__ __forceinline__ uint32_t smem_u32(const void* p) {
    uint32_t a;
    asm("{ .reg .u64 t; cvta.to.shared.u64 t, %1; cvt.u32.u64 %0, t; }" : "=r"(a) : "l"(p));
    return a;
}
__device__ __forceinline__ void ldsm4(uint32_t* r, uint32_t addr) {
    asm volatile("ldmatrix.sync.aligned.m8n8.x4.shared.b16 {%0,%1,%2,%3}, [%4];"
        : "=r"(r[0]), "=r"(r[1]), "=r"(r[2]), "=r"(r[3]) : "r"(addr));
}
__device__ __forceinline__ void mma_bf16(float* c, const uint32_t* a, const uint32_t* b) {
    asm volatile("mma.sync.aligned.m16n8k16.row.col.f32.bf16.bf16.f32 "
        "{%0,%1,%2,%3}, {%4,%5,%6,%7}, {%8,%9}, {%0,%1,%2,%3};"
        : "+f"(c[0]), "+f"(c[1]), "+f"(c[2]), "+f"(c[3])
        : "r"(a[0]), "r"(a[1]), "r"(a[2]), "r"(a[3]), "r"(b[0]), "r"(b[1]));
}
#define MBAR_INIT(mb, c) asm volatile("mbarrier.init.shared.b64 [%0], %1;" :: "r"(mb), "r"(c) : "memory")
#define MBAR_INVAL(mb)   asm volatile("mbarrier.inval.shared.b64 [%0];" :: "r"(mb) : "memory")
#define EXPECT_TX(mb, n) asm volatile("mbarrier.arrive.expect_tx.shared.b64 _, [%0], %1;" :: "r"(mb), "r"(n) : "memory")
#define BULK(dst, src, sz, mb) asm volatile("cp.async.bulk.shared::cta.global.mbarrier::complete_tx::bytes [%0], [%1], %2, [%3];" :: "r"(dst), "l"(src), "r"(sz), "r"(mb) : "memory")
#define MBAR_WAIT(mb, par) do {                                               \
    uint32_t _d;                                                              \
    asm volatile("{\n\t.reg .pred p;\n\t"                                     \
        "mbarrier.try_wait.parity.acquire.cta.shared::cta.b64 p, [%1], %2;\n\t" \
        "selp.b32 %0, 1, 0, p;\n\t}" : "=r"(_d) : "r"(mb), "r"(par) : "memory"); \
    while (!_d) {                                                             \
        asm volatile("{\n\t.reg .pred p;\n\t"                                 \
            "mbarrier.try_wait.parity.acquire.cta.shared::cta.b64 p, [%1], %2, 0x989680;\n\t" \
            "selp.b32 %0, 1, 0, p;\n\t}" : "=r"(_d) : "r"(mb), "r"(par) : "memory"); \
    }                                                                         \
} while (0)

__device__ __forceinline__ uint32_t packbf(float a, float b) {
    __nv_bfloat162 v = __floats2bfloat162_rn(a, b);
    return *(uint32_t*)&v;
}
__device__ __forceinline__ uint32_t f2ord(float f) {
    uint32_t u = __float_as_uint(f);
    return (u & 0x80000000u) ? ~u : (u | 0x80000000u);
}
__device__ __forceinline__ float ord2f(uint32_t o) {
    uint32_t u = (o & 0x80000000u) ? (o ^ 0x80000000u) : ~o;
    return __uint_as_float(u);
}

// ---------- prep: transpose + hi/lo split + SW64-pack weights, K=32 chunks ----------
__global__ void prep_weights(const float* __restrict__ W1, const float* __restrict__ W2) {
    int i = blockIdx.x * 256 + threadIdx.x;
    if (i < EE * HH) {                       // W1[k][n]
        int k = i >> 8, n = i & 255;
        float v = W1[i];
        float hf = __bfloat162float(__float2bfloat16_rn(v));
        unsigned short hb = __bfloat16_as_ushort(__float2bfloat16_rn(v));
        unsigned short lb = __bfloat16_as_ushort(__float2bfloat16_rn(v - hf));
        int half = n >> 7, nn = n & 127, ch = k >> 5, kk = k & 31;
        int base = (half * 16 + ch) * 16384;
        int sw = SWZ64(nn * 64 + kk * 2);
        g_w1pk[(base + sw) >> 1] = hb;
        g_w1pk[(base + 8192 + sw) >> 1] = lb;
    }
    if (i < HH * MM) {                       // W2[k][n]
        int k = i >> 7, n = i & 127;
        float v = W2[i];
        float hf = __bfloat162float(__float2bfloat16_rn(v));
        unsigned short hb = __bfloat16_as_ushort(__float2bfloat16_rn(v));
        unsigned short lb = __bfloat16_as_ushort(__float2bfloat16_rn(v - hf));
        int ch = k >> 5, kk = k & 31;
        int sw = SWZ64(n * 64 + kk * 2);
        g_w2pk[(ch * 16384 + sw) >> 1] = hb;
        g_w2pk[(ch * 16384 + 8192 + sw) >> 1] = lb;
    }
}

// 3-term split-bf16 MMA over one K=32 chunk: acc[2][4][4] += A(32xK) * B(Kx32)^T
// Tiles are [128 rows][32 k] bf16, SW64 swizzled, lo copy at +8192.
__device__ __forceinline__ void mma_chunk32(float acc[2][4][4], uint32_t aBase,
                                            uint32_t wBase, int ra, int rb,
                                            int ca, int cb) {
    #pragma unroll
    for (int k0 = 0; k0 < 32; k0 += 16) {
        uint32_t ah[2][4], al[2][4], bh[4][2], bl[4][2];
        #pragma unroll
        for (int mi = 0; mi < 2; ++mi) {
            uint32_t o = SWZ64((uint32_t)((ra + mi * 16) * 64 + (k0 + ca) * 2));
            ldsm4(ah[mi], aBase + o);
            ldsm4(al[mi], aBase + 8192 + o);
        }
        #pragma unroll
        for (int p = 0; p < 2; ++p) {
            uint32_t o = SWZ64((uint32_t)((rb + p * 16) * 64 + (k0 + cb) * 2));
            uint32_t t4[4];
            ldsm4(t4, wBase + o);
            bh[2 * p][0] = t4[0]; bh[2 * p][1] = t4[1];
            bh[2 * p + 1][0] = t4[2]; bh[2 * p + 1][1] = t4[3];
            ldsm4(t4, wBase + 8192 + o);
            bl[2 * p][0] = t4[0]; bl[2 * p][1] = t4[1];
            bl[2 * p + 1][0] = t4[2]; bl[2 * p + 1][1] = t4[3];
        }
        #pragma unroll
        for (int mi = 0; mi < 2; ++mi)
            #pragma unroll
            for (int ni = 0; ni < 4; ++ni) {
                mma_bf16(acc[mi][ni], ah[mi], bh[ni]);
                mma_bf16(acc[mi][ni], ah[mi], bl[ni]);
                mma_bf16(acc[mi][ni], al[mi], bh[ni]);
            }
    }
}

__global__ void __launch_bounds__(NT, 1)
gene_router_mma(const float* __restrict__ x,
                const int* __restrict__ kpm,
                const float* __restrict__ noise,
                const float* __restrict__ b1,
                const float* __restrict__ b2,
                float* __restrict__ out,
                int write_kpm)
{
    extern __shared__ char smem[];
    const uint32_t smb = smem_u32(smem);
    unsigned* rowx = (unsigned*)(smem + ROWX);
    float* b1s = (float*)(smem + B1S);
    float* b2s = (float*)(smem + B2S);
    float* ls  = (float*)(smem + 0);

    const int t = threadIdx.x;
    const int wid = t >> 5;
    const int lane = t & 31;
    const int rbase = blockIdx.x * 128;
    const int m0 = (wid >> 2) * 32;         // 4-way m split
    const int n0 = (wid & 3) * 32;          // 4-way n split
    const int ra = m0 + (lane & 15);
    const int ca = (lane & 16) >> 1;
    const int rb0 = n0 + (lane & 7) + ((lane & 16) >> 1);
    const int cb = (lane & 8);

    if (t == 0) {
        MBAR_INIT(smb + MB, 1);
        MBAR_INIT(smb + MB + 8, 1);
        asm volatile("fence.mbarrier_init.release.cluster;" ::: "memory");
    }
    if (t < 128) {
        int r = rbase + t;
        unsigned off = 0xFFFFFFFFu;
        if (r < NROWS) {
            int c = r / SSEQ;
            off = (unsigned)((c * LL + (r - c * SSEQ) + 1) * EE);
        }
        rowx[t] = off;
    }
    if (t < 256) b1s[t] = b1[t];
    if (t < 128) b2s[t] = b2[t];
    __syncthreads();

    float4 xv[2];
    #define XLOAD(kc) { _Pragma("unroll") for (int i = 0; i < 2; ++i) {        \
        int s = t + i * NT; int row = s >> 3, c4 = s & 7;                      \
        unsigned off = rowx[row];                                              \
        xv[i] = (off != 0xFFFFFFFFu)                                           \
            ? *(const float4*)(x + off + (kc) * 32 + c4 * 4)                   \
            : make_float4(0.f, 0.f, 0.f, 0.f); } }
    #define XSTORE(buf) { _Pragma("unroll") for (int i = 0; i < 2; ++i) {      \
        int s = t + i * NT; int row = s >> 3, c4 = s & 7; float4 v = xv[i];    \
        float h0 = __bfloat162float(__float2bfloat16_rn(v.x));                 \
        float h1 = __bfloat162float(__float2bfloat16_rn(v.y));                 \
        float h2 = __bfloat162float(__float2bfloat16_rn(v.z));                 \
        float h3 = __bfloat162float(__float2bfloat16_rn(v.w));                 \
        uint32_t o = XS + (buf) * 16384 + (uint32_t)SWZ64(row * 64 + c4 * 8);  \
        *(uint2*)(smem + o) = make_uint2(packbf(v.x, v.y), packbf(v.z, v.w));  \
        *(uint2*)(smem + o + 8192) =                                           \
            make_uint2(packbf(v.x - h0, v.y - h1), packbf(v.z - h2, v.w - h3)); } }
    #define ISSUE(ci) if (t == 0 && (ci) < 40) {                               \
        uint32_t dst = smb + WB + ((ci) & 1) * 16384;                          \
        const char* src = ((ci) < 32)                                          \
            ? ((const char*)g_w1pk + (size_t)(ci) * 16384)                     \
            : ((const char*)g_w2pk + (size_t)((ci) - 32) * 16384);             \
        uint32_t m = smb + MB + ((ci) & 1) * 8;                                \
        EXPECT_TX(m, 16384u); BULK(dst, src, 16384u, m); }
    #define WAITW(ci) MBAR_WAIT(smb + MB + ((ci) & 1) * 8, ((ci) >> 1) & 1)

    float acc[2][4][4];
    #pragma unroll
    for (int i = 0; i < 32; ++i) ((float*)acc)[i] = 0.f;

    ISSUE(0)
    XLOAD(0)
    XSTORE(0)
    __syncthreads();

    // ---- layer 1: two H-halves x 16 K-chunks (K=32) ----
    #pragma unroll 1
    for (int half = 0; half < 2; ++half) {
        #pragma unroll 1
        for (int c = 0; c < 16; ++c) {
            const int ci = half * 16 + c;
            ISSUE(ci + 1)
            const int morex = (ci + 1 < 32);
            if (morex) { XLOAD((c + 1) & 15) }    // LDG in flight during wait+mma
            WAITW(ci);
            mma_chunk32(acc, smb + XS + (ci & 1) * 16384,
                        smb + WB + (ci & 1) * 16384, ra, rb0, ca, cb);
            if (morex) { XSTORE((ci + 1) & 1) }
            __syncthreads();
        }
        // epilogue 1: h = relu(D1 + b1) -> split bf16 -> HB chunks (K=32 layout)
        #pragma unroll
        for (int mi = 0; mi < 2; ++mi)
            #pragma unroll
            for (int ni = 0; ni < 4; ++ni) {
                int n = half * 128 + n0 + ni * 8 + (lane & 3) * 2;
                int r1 = m0 + mi * 16 + (lane >> 2);
                float f0 = fmaxf(acc[mi][ni][0] + b1s[n], 0.f);
                float f1 = fmaxf(acc[mi][ni][1] + b1s[n + 1], 0.f);
                float f2 = fmaxf(acc[mi][ni][2] + b1s[n], 0.f);
                float f3 = fmaxf(acc[mi][ni][3] + b1s[n + 1], 0.f);
                float g0 = __bfloat162float(__float2bfloat16_rn(f0));
                float g1 = __bfloat162float(__float2bfloat16_rn(f1));
                float g2 = __bfloat162float(__float2bfloat16_rn(f2));
                float g3 = __bfloat162float(__float2bfloat16_rn(f3));
                int ch = n >> 5, kk = n & 31;
                uint32_t o1 = HB + ch * 16384 + SWZ64((uint32_t)(r1 * 64 + kk * 2));
                uint32_t o2 = HB + ch * 16384 + SWZ64((uint32_t)((r1 + 8) * 64 + kk * 2));
                *(uint32_t*)(smem + o1) = packbf(f0, f1);
                *(uint32_t*)(smem + o1 + 8192) = packbf(f0 - g0, f1 - g1);
                *(uint32_t*)(smem + o2) = packbf(f2, f3);
                *(uint32_t*)(smem + o2 + 8192) = packbf(f2 - g2, f3 - g3);
                acc[mi][ni][0] = acc[mi][ni][1] = acc[mi][ni][2] = acc[mi][ni][3] = 0.f;
            }
        __syncthreads();
    }

    // ---- layer 2: 8 K=32 chunks over h ----
    #pragma unroll 1
    for (int c = 0; c < 8; ++c) {
        const int ci = 32 + c;
        ISSUE(ci + 1)
        WAITW(ci);
        mma_chunk32(acc, smb + HB + c * 16384,
                    smb + WB + (ci & 1) * 16384, ra, rb0, ca, cb);
        __syncthreads();
    }

    // ---- epilogue 2: logits -> ls ----
    #pragma unroll
    for (int mi = 0; mi < 2; ++mi)
        #pragma unroll
        for (int ni = 0; ni < 4; ++ni) {
            int n = n0 + ni * 8 + (lane & 3) * 2;
            int r1 = m0 + mi * 16 + (lane >> 2);
            *(float2*)(smem + r1 * 528 + n * 4) =
                make_float2(acc[mi][ni][0] + b2s[n], acc[mi][ni][1] + b2s[n + 1]);
            *(float2*)(smem + (r1 + 8) * 528 + n * 4) =
                make_float2(acc[mi][ni][2] + b2s[n], acc[mi][ni][3] + b2s[n + 1]);
        }
    __syncthreads();

    // ---- phase 3: gumbel + softmax + exact top-30 + smooth mask ----
    #pragma unroll 1
    for (int lr = wid * 8; lr < wid * 8 + 8; ++lr) {
        int r = rbase + lr;
        if (r >= NROWS) break;

        float4 lg = *(const float4*)(ls + lr * LSTR + lane * 4);
        float4 nz = *(const float4*)(noise + (size_t)r * MM + lane * 4);
        float pert[4];
        pert[0] = lg.x - logf(-logf(nz.x + 1e-20f) + 1e-20f);
        pert[1] = lg.y - logf(-logf(nz.y + 1e-20f) + 1e-20f);
        pert[2] = lg.z - logf(-logf(nz.z + 1e-20f) + 1e-20f);
        pert[3] = lg.w - logf(-logf(nz.w + 1e-20f) + 1e-20f);

        float mx = fmaxf(fmaxf(pert[0], pert[1]), fmaxf(pert[2], pert[3]));
        #pragma unroll
        for (int o = 16; o > 0; o >>= 1)
            mx = fmaxf(mx, __shfl_xor_sync(0xFFFFFFFFu, mx, o));

        float e0 = expf(pert[0] - mx), e1 = expf(pert[1] - mx);
        float e2 = expf(pert[2] - mx), e3 = expf(pert[3] - mx);
        float sum = e0 + e1 + e2 + e3;
        #pragma unroll
        for (int o = 16; o > 0; o >>= 1)
            sum += __shfl_xor_sync(0xFFFFFFFFu, sum, o);

        uint32_t k0 = f2ord(pert[0]), k1 = f2ord(pert[1]);
        uint32_t k2 = f2ord(pert[2]), k3 = f2ord(pert[3]);
        uint32_t th = 0u;
        #pragma unroll 1
        for (int b = 31; b >= 0; --b) {
            uint32_t t2 = th | (1u << b);
            int cnt = (k0 >= t2) + (k1 >= t2) + (k2 >= t2) + (k3 >= t2);
            cnt = __reduce_add_sync(0xFFFFFFFFu, cnt);
            if (cnt >= TOPK) th = t2;
        }

        float inv = 1.0f / sum;
        float tpb = expf(ord2f(th) - mx) * inv;
        int kp = kpm[rowx[lr] >> 9];
        float keep = (kp != 0) ? 0.f : 1.f;

        float4 o4;
        float p = e0 * inv; o4.x = p * (1.0f / (1.0f + expf((tpb - p) * 100.0f))) * keep;
        p = e1 * inv;       o4.y = p * (1.0f / (1.0f + expf((tpb - p) * 100.0f))) * keep;
        p = e2 * inv;       o4.z = p * (1.0f / (1.0f + expf((tpb - p) * 100.0f))) * keep;
        p = e3 * inv;       o4.w = p * (1.0f / (1.0f + expf((tpb - p) * 100.0f))) * keep;
        *(float4*)(out + (size_t)r * MM + lane * 4) = o4;

        if (lane == 0 && write_kpm)
            out[(size_t)NROWS * MM + r] = (kp != 0) ? 1.f : 0.f;
    }
    __syncthreads();
    if (t == 0) { MBAR_INVAL(smb + MB); MBAR_INVAL(smb + MB + 8); }
}

extern "C" void kernel_launch(void* const* d_in, const int* in_sizes, int n_in,
                              void* d_out, int out_size) {
    const float* x     = (const float*)d_in[0];
    const int*   kpm   = (const int*)d_in[1];
    const float* noise = (const float*)d_in[2];
    const float* W1    = (const float*)d_in[3];
    const float* b1    = (const float*)d_in[4];
    const float* W2    = (const float*)d_in[5];
    const float* b2    = (const float*)d_in[6];
    float* out = (float*)d_out;

    int write_kpm = (out_size >= NROWS * MM + NROWS) ? 1 : 0;

    prep_weights<<<(EE * HH + 255) / 256, 256>>>(W1, W2);

    cudaFuncSetAttribute(gene_router_mma,
                         cudaFuncAttributeMaxDynamicSharedMemorySize, SMEMB);
    gene_router_mma<<<(NROWS + 127) / 128, NT, SMEMB>>>(
        x, kpm, noise, b1, b2, out, write_kpm);
}

// round 10
// speedup vs baseline: 1.0029x; 1.0029x over previous
#include <cuda_runtime.h>
#include <cuda_bf16.h>
#include <cstdint>

#define CC 16
#define LL 8192
#define EE 512
#define HH 256
#define MM 128
#define TOPK 30
#define SSEQ 8191
#define NROWS 131056
#define NT 512

// smem byte offsets
#define HB 0                 // h split: 8 chunks x [hi 8KB | lo 8KB] = 128KB
#define XS 131072            // X split ping-pong: 2 x 16KB
#define WB 163840            // W ping-pong: 2 x 16KB
#define ROWX 196608
#define B1S 197120
#define B2S 198144
#define MB 198656            // 2 mbarriers
#define SMEMB 198784
#define LSTR 132

#define SWZ64(o) ((o) ^ (((o) >> 3) & 0x30))

__device__ unsigned short g_w1pk[262144];  // 512KB: 32 chunks x [hi 8KB | lo 8KB], n-major [128n][32k]
__device__ unsigned short g_w2pk[65536];   // 128KB: 8 chunks x [hi | lo]

__device__ __forceinline__ uint32_t smem_u32(const void* p) {
    uint32_t a;
    asm("{ .reg .u64 t; cvta.to.shared.u64 t, %1; cvt.u32.u64 %0, t; }" : "=r"(a) : "l"(p));
    return a;
}
__device__ __forceinline__ void ldsm4(uint32_t* r, uint32_t addr) {
    asm volatile("ldmatrix.sync.aligned.m8n8.x4.shared.b16 {%0,%1,%2,%3}, [%4];"
        : "=r"(r[0]), "=r"(r[1]), "=r"(r[2]), "=r"(r[3]) : "r"(addr));
}
__device__ __forceinline__ void mma_bf16(float* c, const uint32_t* a, const uint32_t* b) {
    asm volatile("mma.sync.aligned.m16n8k16.row.col.f32.bf16.bf16.f32 "
        "{%0,%1,%2,%3}, {%4,%5,%6,%7}, {%8,%9}, {%0,%1,%2,%3};"
        : "+f"(c[0]), "+f"(c[1]), "+f"(c[2]), "+f"(c[3])
        : "r"(a[0]), "r"(a[1]), "r"(a[2]), "r"(a[3]), "r"(b[0]), "r"(b[1]));
}
#define MBAR_INIT(mb, c) asm volatile("mbarrier.init.shared.b64 [%0], %1;" :: "r"(mb), "r"(c) : "memory")
#define MBAR_INVAL(mb)   asm volatile("mbarrier.inval.shared.b64 [%0];" :: "r"(mb) : "memory")
#define EXPECT_TX(mb, n) asm volatile("mbarrier.arrive.expect_tx.shared.b64 _, [%0], %1;" :: "r"(mb), "r"(n) : "memory")
#define BULK(dst, src, sz, mb) asm volatile("cp.async.bulk.shared::cta.global.mbarrier::complete_tx::bytes [%0], [%1], %2, [%3];" :: "r"(dst), "l"(src), "r"(sz), "r"(mb) : "memory")
#define MBAR_WAIT(mb, par) do {                                               \
    uint32_t _d;                                                              \
    asm volatile("{\n\t.reg .pred p;\n\t"                                     \
        "mbarrier.try_wait.parity.acquire.cta.shared::cta.b64 p, [%1], %2;\n\t" \
        "selp.b32 %0, 1, 0, p;\n\t}" : "=r"(_d) : "r"(mb), "r"(par) : "memory"); \
    while (!_d) {                                                             \
        asm volatile("{\n\t.reg .pred p;\n\t"                                 \
            "mbarrier.try_wait.parity.acquire.cta.shared::cta.b64 p, [%1], %2, 0x989680;\n\t" \
            "selp.b32 %0, 1, 0, p;\n\t}" : "=r"(_d) : "r"(mb), "r"(par) : "memory"); \
    }                                                                         \
} while (0)

__device__ __forceinline__ uint32_t packbf(float a, float b) {
    __nv_bfloat162 v = __floats2bfloat162_rn(a, b);
    return *(uint32_t*)&v;
}
__device__ __forceinline__ uint32_t f2ord(float f) {
    uint32_t u = __float_as_uint(f);
    return (u & 0x80000000u) ? ~u : (u | 0x80000000u);
}
__device__ __forceinline__ float ord2f(uint32_t o) {
    uint32_t u = (o & 0x80000000u) ? (o ^ 0x80000000u) : ~o;
    return __uint_as_float(u);
}

// ---------- prep: transpose + hi/lo split + SW64-pack weights, K=32 chunks ----------
__global__ void prep_weights(const float* __restrict__ W1, const float* __restrict__ W2) {
    int i = blockIdx.x * 256 + threadIdx.x;
    if (i < EE * HH) {                       // W1[k][n]
        int k = i >> 8, n = i & 255;
        float v = W1[i];
        float hf = __bfloat162float(__float2bfloat16_rn(v));
        unsigned short hb = __bfloat16_as_ushort(__float2bfloat16_rn(v));
        unsigned short lb = __bfloat16_as_ushort(__float2bfloat16_rn(v - hf));
        int half = n >> 7, nn = n & 127, ch = k >> 5, kk = k & 31;
        int base = (half * 16 + ch) * 16384;
        int sw = SWZ64(nn * 64 + kk * 2);
        g_w1pk[(base + sw) >> 1] = hb;
        g_w1pk[(base + 8192 + sw) >> 1] = lb;
    }
    if (i < HH * MM) {                       // W2[k][n]
        int k = i >> 7, n = i & 127;
        float v = W2[i];
        float hf = __bfloat162float(__float2bfloat16_rn(v));
        unsigned short hb = __bfloat16_as_ushort(__float2bfloat16_rn(v));
        unsigned short lb = __bfloat16_as_ushort(__float2bfloat16_rn(v - hf));
        int ch = k >> 5, kk = k & 31;
        int sw = SWZ64(n * 64 + kk * 2);
        g_w2pk[(ch * 16384 + sw) >> 1] = hb;
        g_w2pk[(ch * 16384 + 8192 + sw) >> 1] = lb;
    }
}

// 3-term split-bf16 MMA over one K=32 chunk: acc[2][4][4] += A(32xK) * B(Kx32)^T
// Tiles are [128 rows][32 k] bf16, SW64 swizzled, lo copy at +8192.
__device__ __forceinline__ void mma_chunk32(float acc[2][4][4], uint32_t aBase,
                                            uint32_t wBase, int ra, int rb,
                                            int ca, int cb) {
    #pragma unroll
    for (int k0 = 0; k0 < 32; k0 += 16) {
        uint32_t ah[2][4], al[2][4], bh[4][2], bl[4][2];
        #pragma unroll
        for (int mi = 0; mi < 2; ++mi) {
            uint32_t o = SWZ64((uint32_t)((ra + mi * 16) * 64 + (k0 + ca) * 2));
            ldsm4(ah[mi], aBase + o);
            ldsm4(al[mi], aBase + 8192 + o);
        }
        #pragma unroll
        for (int p = 0; p < 2; ++p) {
            uint32_t o = SWZ64((uint32_t)((rb + p * 16) * 64 + (k0 + cb) * 2));
            uint32_t t4[4];
            ldsm4(t4, wBase + o);
            bh[2 * p][0] = t4[0]; bh[2 * p][1] = t4[1];
            bh[2 * p + 1][0] = t4[2]; bh[2 * p + 1][1] = t4[3];
            ldsm4(t4, wBase + 8192 + o);
            bl[2 * p][0] = t4[0]; bl[2 * p][1] = t4[1];
            bl[2 * p + 1][0] = t4[2]; bl[2 * p + 1][1] = t4[3];
        }
        #pragma unroll
        for (int mi = 0; mi < 2; ++mi)
            #pragma unroll
            for (int ni = 0; ni < 4; ++ni) {
                mma_bf16(acc[mi][ni], ah[mi], bh[ni]);
                mma_bf16(acc[mi][ni], ah[mi], bl[ni]);
                mma_bf16(acc[mi][ni], al[mi], bh[ni]);
            }
    }
}

__global__ void __launch_bounds__(NT, 1)
gene_router_mma(const float* __restrict__ x,
                const int* __restrict__ kpm,
                const float* __restrict__ noise,
                const float* __restrict__ b1,
                const float* __restrict__ b2,
                float* __restrict__ out,
                int write_kpm)
{
    extern __shared__ char smem[];
    const uint32_t smb = smem_u32(smem);
    unsigned* rowx = (unsigned*)(smem + ROWX);
    float* b1s = (float*)(smem + B1S);
    float* b2s = (float*)(smem + B2S);
    float* ls  = (float*)(smem + 0);

    const int t = threadIdx.x;
    const int wid = t >> 5;
    const int lane = t & 31;
    const int rbase = blockIdx.x * 128;
    const int m0 = (wid >> 2) * 32;         // 4-way m split
    const int n0 = (wid & 3) * 32;          // 4-way n split
    const int ra = m0 + (lane & 15);
    const int ca = (lane & 16) >> 1;
    const int rb0 = n0 + (lane & 7) + ((lane & 16) >> 1);
    const int cb = (lane & 8);

    if (t == 0) {
        MBAR_INIT(smb + MB, 1);
        MBAR_INIT(smb + MB + 8, 1);
        asm volatile("fence.mbarrier_init.release.cluster;" ::: "memory");
    }
    if (t < 128) {
        int r = rbase + t;
        unsigned off = 0xFFFFFFFFu;
        if (r < NROWS) {
            int c = r / SSEQ;
            off = (unsigned)((c * LL + (r - c * SSEQ) + 1) * EE);
        }
        rowx[t] = off;
    }
    if (t < 256) b1s[t] = b1[t];
    if (t < 128) b2s[t] = b2[t];
    __syncthreads();

    float4 xv[2];
    #define XLOAD(kc) { _Pragma("unroll") for (int i = 0; i < 2; ++i) {        \
        int s = t + i * NT; int row = s >> 3, c4 = s & 7;                      \
        unsigned off = rowx[row];                                              \
        xv[i] = (off != 0xFFFFFFFFu)                                           \
            ? *(const float4*)(x + off + (kc) * 32 + c4 * 4)                   \
            : make_float4(0.f, 0.f, 0.f, 0.f); } }
    #define XSTORE(buf) { _Pragma("unroll") for (int i = 0; i < 2; ++i) {      \
        int s = t + i * NT; int row = s >> 3, c4 = s & 7; float4 v = xv[i];    \
        float h0 = __bfloat162float(__float2bfloat16_rn(v.x));                 \
        float h1 = __bfloat162float(__float2bfloat16_rn(v.y));                 \
        float h2 = __bfloat162float(__float2bfloat16_rn(v.z));                 \
        float h3 = __bfloat162float(__float2bfloat16_rn(v.w));                 \
        uint32_t o = XS + (buf) * 16384 + (uint32_t)SWZ64(row * 64 + c4 * 8);  \
        *(uint2*)(smem + o) = make_uint2(packbf(v.x, v.y), packbf(v.z, v.w));  \
        *(uint2*)(smem + o + 8192) =                                           \
            make_uint2(packbf(v.x - h0, v.y - h1), packbf(v.z - h2, v.w - h3)); } }
    #define ISSUE(ci) if (t == 0 && (ci) < 40) {                               \
        uint32_t dst = smb + WB + ((ci) & 1) * 16384;                          \
        const char* src = ((ci) < 32)                                          \
            ? ((const char*)g_w1pk + (size_t)(ci) * 16384)                     \
            : ((const char*)g_w2pk + (size_t)((ci) - 32) * 16384);             \
        uint32_t m = smb + MB + ((ci) & 1) * 8;                                \
        EXPECT_TX(m, 16384u); BULK(dst, src, 16384u, m); }
    #define WAITW(ci) MBAR_WAIT(smb + MB + ((ci) & 1) * 8, ((ci) >> 1) & 1)

    float acc[2][4][4];
    #pragma unroll
    for (int i = 0; i < 32; ++i) ((float*)acc)[i] = 0.f;

    ISSUE(0)
    XLOAD(0)
    XSTORE(0)
    __syncthreads();

    // ---- layer 1: two H-halves x 16 K-chunks (K=32) ----
    #pragma unroll 1
    for (int half = 0; half < 2; ++half) {
        #pragma unroll 1
        for (int c = 0; c < 16; ++c) {
            const int ci = half * 16 + c;
            ISSUE(ci + 1)
            const int morex = (ci + 1 < 32);
            if (morex) { XLOAD((c + 1) & 15) }    // LDG in flight during wait+mma
            WAITW(ci);
            mma_chunk32(acc, smb + XS + (ci & 1) * 16384,
                        smb + WB + (ci & 1) * 16384, ra, rb0, ca, cb);
            if (morex) { XSTORE((ci + 1) & 1) }
            __syncthreads();
        }
        // epilogue 1: h = relu(D1 + b1) -> split bf16 -> HB chunks (K=32 layout)
        #pragma unroll
        for (int mi = 0; mi < 2; ++mi)
            #pragma unroll
            for (int ni = 0; ni < 4; ++ni) {
                int n = half * 128 + n0 + ni * 8 + (lane & 3) * 2;
                int r1 = m0 + mi * 16 + (lane >> 2);
                float f0 = fmaxf(acc[mi][ni][0] + b1s[n], 0.f);
                float f1 = fmaxf(acc[mi][ni][1] + b1s[n + 1], 0.f);
                float f2 = fmaxf(acc[mi][ni][2] + b1s[n], 0.f);
                float f3 = fmaxf(acc[mi][ni][3] + b1s[n + 1], 0.f);
                float g0 = __bfloat162float(__float2bfloat16_rn(f0));
                float g1 = __bfloat162float(__float2bfloat16_rn(f1));
                float g2 = __bfloat162float(__float2bfloat16_rn(f2));
                float g3 = __bfloat162float(__float2bfloat16_rn(f3));
                int ch = n >> 5, kk = n & 31;
                uint32_t o1 = HB + ch * 16384 + SWZ64((uint32_t)(r1 * 64 + kk * 2));
                uint32_t o2 = HB + ch * 16384 + SWZ64((uint32_t)((r1 + 8) * 64 + kk * 2));
                *(uint32_t*)(smem + o1) = packbf(f0, f1);
                *(uint32_t*)(smem + o1 + 8192) = packbf(f0 - g0, f1 - g1);
                *(uint32_t*)(smem + o2) = packbf(f2, f3);
                *(uint32_t*)(smem + o2 + 8192) = packbf(f2 - g2, f3 - g3);
                acc[mi][ni][0] = acc[mi][ni][1] = acc[mi][ni][2] = acc[mi][ni][3] = 0.f;
            }
        __syncthreads();
    }

    // ---- layer 2: 8 K=32 chunks over h ----
    #pragma unroll 1
    for (int c = 0; c < 8; ++c) {
        const int ci = 32 + c;
        ISSUE(ci + 1)
        WAITW(ci);
        mma_chunk32(acc, smb + HB + c * 16384,
                    smb + WB + (ci & 1) * 16384, ra, rb0, ca, cb);
        __syncthreads();
    }

    // ---- epilogue 2: logits -> ls ----
    #pragma unroll
    for (int mi = 0; mi < 2; ++mi)
        #pragma unroll
        for (int ni = 0; ni < 4; ++ni) {
            int n = n0 + ni * 8 + (lane & 3) * 2;
            int r1 = m0 + mi * 16 + (lane >> 2);
            *(float2*)(smem + r1 * 528 + n * 4) =
                make_float2(acc[mi][ni][0] + b2s[n], acc[mi][ni][1] + b2s[n + 1]);
            *(float2*)(smem + (r1 + 8) * 528 + n * 4) =
                make_float2(acc[mi][ni][2] + b2s[n], acc[mi][ni][3] + b2s[n + 1]);
        }
    __syncthreads();

    // ---- phase 3: gumbel + softmax + exact top-30 + smooth mask ----
    #pragma unroll 1
    for (int lr = wid * 8; lr < wid * 8 + 8; ++lr) {
        int r = rbase + lr;
        if (r >= NROWS) break;

        float4 lg = *(const float4*)(ls + lr * LSTR + lane * 4);
        float4 nz = *(const float4*)(noise + (size_t)r * MM + lane * 4);
        float pert[4];
        pert[0] = lg.x - logf(-logf(nz.x + 1e-20f) + 1e-20f);
        pert[1] = lg.y - logf(-logf(nz.y + 1e-20f) + 1e-20f);
        pert[2] = lg.z - logf(-logf(nz.z + 1e-20f) + 1e-20f);
        pert[3] = lg.w - logf(-logf(nz.w + 1e-20f) + 1e-20f);

        float mx = fmaxf(fmaxf(pert[0], pert[1]), fmaxf(pert[2], pert[3]));
        #pragma unroll
        for (int o = 16; o > 0; o >>= 1)
            mx = fmaxf(mx, __shfl_xor_sync(0xFFFFFFFFu, mx, o));

        float e0 = expf(pert[0] - mx), e1 = expf(pert[1] - mx);
        float e2 = expf(pert[2] - mx), e3 = expf(pert[3] - mx);
        float sum = e0 + e1 + e2 + e3;
        #pragma unroll
        for (int o = 16; o > 0; o >>= 1)
            sum += __shfl_xor_sync(0xFFFFFFFFu, sum, o);

        uint32_t k0 = f2ord(pert[0]), k1 = f2ord(pert[1]);
        uint32_t k2 = f2ord(pert[2]), k3 = f2ord(pert[3]);
        uint32_t th = 0u;
        #pragma unroll 1
        for (int b = 31; b >= 0; --b) {
            uint32_t t2 = th | (1u << b);
            int cnt = (k0 >= t2) + (k1 >= t2) + (k2 >= t2) + (k3 >= t2);
            cnt = __reduce_add_sync(0xFFFFFFFFu, cnt);
            if (cnt >= TOPK) th = t2;
        }

        float inv = 1.0f / sum;
        float tpb = expf(ord2f(th) - mx) * inv;
        int kp = kpm[rowx[lr] >> 9];
        float keep = (kp != 0) ? 0.f : 1.f;

        float4 o4;
        float p = e0 * inv; o4.x = p * (1.0f / (1.0f + expf((tpb - p) * 100.0f))) * keep;
        p = e1 * inv;       o4.y = p * (1.0f / (1.0f + expf((tpb - p) * 100.0f))) * keep;
        p = e2 * inv;       o4.z = p * (1.0f / (1.0f + expf((tpb - p) * 100.0f))) * keep;
        p = e3 * inv;       o4.w = p * (1.0f / (1.0f + expf((tpb - p) * 100.0f))) * keep;
        *(float4*)(out + (size_t)r * MM + lane * 4) = o4;

        if (lane == 0 && write_kpm)
            out[(size_t)NROWS * MM + r] = (kp != 0) ? 1.f : 0.f;
    }
    __syncthreads();
    if (t == 0) { MBAR_INVAL(smb + MB); MBAR_INVAL(smb + MB + 8); }
}

extern "C" void kernel_launch(void* const* d_in, const int* in_sizes, int n_in,
                              void* d_out, int out_size) {
    const float* x     = (const float*)d_in[0];
    const int*   kpm   = (const int*)d_in[1];
    const float* noise = (const float*)d_in[2];
    const float* W1    = (const float*)d_in[3];
    const float* b1    = (const float*)d_in[4];
    const float* W2    = (const float*)d_in[5];
    const float* b2    = (const float*)d_in[6];
    float* out = (float*)d_out;

    int write_kpm = (out_size >= NROWS * MM + NROWS) ? 1 : 0;

    prep_weights<<<(EE * HH + 255) / 256, 256>>>(W1, W2);

    cudaFuncSetAttribute(gene_router_mma,
                         cudaFuncAttributeMaxDynamicSharedMemorySize, SMEMB);
    gene_router_mma<<<(NROWS + 127) / 128, NT, SMEMB>>>(
        x, kpm, noise, b1, b2, out, write_kpm);
}